// round 16
// baseline (speedup 1.0000x reference)
#include <cuda_runtime.h>
#include <cuda_fp16.h>
#include <cstdint>
#include <cmath>

#define BB 8
#define TT 2048
#define CC 1024

typedef __half f16;

// Scratch (device globals — allocation-free)
__device__ f16    g_xhi  [(size_t)BB * TT * CC];
__device__ f16    g_xlo  [(size_t)BB * TT * CC];
__device__ f16    g_whi  [(size_t)CC * CC];
__device__ f16    g_wlo  [(size_t)CC * CC];
__device__ f16    g_xHhi [(size_t)BB * TT * CC];
__device__ f16    g_xHlo [(size_t)BB * TT * CC];
__device__ float  g_sc   [(size_t)BB * TT * TT];
__device__ f16    g_wei  [(size_t)BB * TT * TT];

// ===========================================================================
// helpers
// ===========================================================================
__device__ __forceinline__ uint32_t smem_u32(const void* p) {
    uint32_t a;
    asm("{ .reg .u64 t; cvta.to.shared.u64 t, %1; cvt.u32.u64 %0, t; }" : "=r"(a) : "l"(p));
    return a;
}
__device__ __forceinline__ void cp16(uint32_t s, const void* g) {
    asm volatile("cp.async.cg.shared.global [%0], [%1], 16;" :: "r"(s), "l"(g) : "memory");
}
__device__ __forceinline__ void ldsm4(uint32_t addr, uint32_t& r0, uint32_t& r1,
                                      uint32_t& r2, uint32_t& r3) {
    asm volatile("ldmatrix.sync.aligned.m8n8.x4.shared.b16 {%0,%1,%2,%3}, [%4];"
                 : "=r"(r0), "=r"(r1), "=r"(r2), "=r"(r3) : "r"(addr));
}
__device__ __forceinline__ void ldsm4t(uint32_t addr, uint32_t& r0, uint32_t& r1,
                                       uint32_t& r2, uint32_t& r3) {
    asm volatile("ldmatrix.sync.aligned.m8n8.x4.trans.shared.b16 {%0,%1,%2,%3}, [%4];"
                 : "=r"(r0), "=r"(r1), "=r"(r2), "=r"(r3) : "r"(addr));
}
__device__ __forceinline__ void mma_f16(float c[4], const uint32_t a[4], const uint32_t b[2]) {
    asm volatile(
        "mma.sync.aligned.m16n8k16.row.col.f32.f16.f16.f32 "
        "{%0,%1,%2,%3}, {%4,%5,%6,%7}, {%8,%9}, {%0,%1,%2,%3};"
        : "+f"(c[0]), "+f"(c[1]), "+f"(c[2]), "+f"(c[3])
        : "r"(a[0]), "r"(a[1]), "r"(a[2]), "r"(a[3]), "r"(b[0]), "r"(b[1]));
}
__device__ __forceinline__ void stg_cs_f2(float* p, float a, float b) {
    asm volatile("st.global.cs.v2.f32 [%0], {%1, %2};" :: "l"(p), "f"(a), "f"(b) : "memory");
}
__device__ __forceinline__ float4 ldg_cs_f4(const float* p) {
    float4 v;
    asm volatile("ld.global.cs.v4.f32 {%0,%1,%2,%3}, [%4];"
                 : "=f"(v.x), "=f"(v.y), "=f"(v.z), "=f"(v.w) : "l"(p));
    return v;
}

// swizzled 16B-chunk offset within a 128x32-f16 (64B-row) K-major tile
__device__ __forceinline__ uint32_t swz(int row, int chunk) {
    return (uint32_t)(row * 64 + ((chunk ^ ((row >> 1) & 3)) << 4));
}

// ===========================================================================
// 3xFP16 GEMM:  C = A[M,K] @ B[N,K]^T, fp16 hi/lo inputs, 128x128 tile, KC=32
// 3-stage cp.async pipeline, swizzled 64B rows, 2 CTAs/SM.
// CAUSAL: 1-D lower-triangle grid. OUTMODE: 0 = fp32 (.cs), 2 = fp16 hi/lo.
// ===========================================================================
#define AHI_OFF 0
#define ALO_OFF 8192
#define BHI_OFF 16384
#define BLO_OFF 24576
#define STG_BYTES 32768
#define SMEM_TOTAL (3 * STG_BYTES)   // 98304

template <bool CAUSAL, int OUTMODE>
__global__ __launch_bounds__(256, 2) void gemm_3x(
    const f16* __restrict__ Ahi, const f16* __restrict__ Alo,
    const f16* __restrict__ Bhi, const f16* __restrict__ Blo,
    float* __restrict__ Cf, f16* __restrict__ Chi, f16* __restrict__ Clo,
    int lda, int ldb, int ldc, int Kfull,
    long long sA, long long sB, long long sC)
{
    int bx, by;
    const int bz = blockIdx.z;
    if (CAUSAL) {
        const int idx = blockIdx.x;
        int t = (int)((sqrtf(8.0f * idx + 1.0f) - 1.0f) * 0.5f);
        while ((t + 1) * (t + 2) / 2 <= idx) t++;
        while (t * (t + 1) / 2 > idx) t--;
        by = t;
        bx = idx - t * (t + 1) / 2;
    } else {
        bx = blockIdx.x; by = blockIdx.y;
    }

    Ahi += (long long)bz * sA; Alo += (long long)bz * sA;
    Bhi += (long long)bz * sB; Blo += (long long)bz * sB;

    const int m0 = by * 128, n0 = bx * 128;
    const int nc = Kfull / 32;

    extern __shared__ char smem[];
    const uint32_t sbase = smem_u32(smem);
    const int tid = threadIdx.x;
    const int wid = tid >> 5, lane = tid & 31;
    const int wm = wid & 1, wn = wid >> 1;
    const int g = lane >> 3, i = lane & 7;

    const int arow_base = wm * 64 + i + (g & 1) * 8;
    const int brow_base = wn * 32 + i + (g >> 1) * 8;
    const int achunk0 = g >> 1;
    const int bchunk0 = g & 1;

    const int l_row = tid >> 2, l_ch = tid & 3;
    const uint32_t l_soff0 = swz(l_row, l_ch);
    const uint32_t l_soff1 = swz(l_row + 64, l_ch);

    float acc[4][4][4];
#pragma unroll
    for (int a = 0; a < 4; a++)
#pragma unroll
        for (int b = 0; b < 4; b++)
#pragma unroll
            for (int c = 0; c < 4; c++) acc[a][b][c] = 0.f;

    auto issue = [&](int ch) {
        const uint32_t st = sbase + (uint32_t)(ch % 3) * STG_BYTES;
        const long long k0 = (long long)ch * 32 + l_ch * 8;
        {
            const long long ga = (long long)(m0 + l_row) * lda + k0;
            const long long gb = (long long)(n0 + l_row) * ldb + k0;
            cp16(st + AHI_OFF + l_soff0, Ahi + ga);
            cp16(st + ALO_OFF + l_soff0, Alo + ga);
            cp16(st + BHI_OFF + l_soff0, Bhi + gb);
            cp16(st + BLO_OFF + l_soff0, Blo + gb);
        }
        {
            const long long ga = (long long)(m0 + l_row + 64) * lda + k0;
            const long long gb = (long long)(n0 + l_row + 64) * ldb + k0;
            cp16(st + AHI_OFF + l_soff1, Ahi + ga);
            cp16(st + ALO_OFF + l_soff1, Alo + ga);
            cp16(st + BHI_OFF + l_soff1, Bhi + gb);
            cp16(st + BLO_OFF + l_soff1, Blo + gb);
        }
    };

#pragma unroll
    for (int s = 0; s < 2; s++) {
        if (s < nc) issue(s);
        asm volatile("cp.async.commit_group;" ::: "memory");
    }

    for (int ch = 0; ch < nc; ch++) {
        asm volatile("cp.async.wait_group 1;" ::: "memory");
        __syncthreads();
        if (ch + 2 < nc) issue(ch + 2);
        asm volatile("cp.async.commit_group;" ::: "memory");

        const uint32_t st = sbase + (uint32_t)(ch % 3) * STG_BYTES;

#pragma unroll
        for (int ks = 0; ks < 2; ks++) {
            uint32_t ah[4][4], al[4][4], bh[4][2], bl[4][2];
#pragma unroll
            for (int mt = 0; mt < 4; mt++) {
                const uint32_t ao = swz(arow_base + mt * 16, achunk0 + ks * 2);
                ldsm4(st + AHI_OFF + ao, ah[mt][0], ah[mt][1], ah[mt][2], ah[mt][3]);
                ldsm4(st + ALO_OFF + ao, al[mt][0], al[mt][1], al[mt][2], al[mt][3]);
            }
#pragma unroll
            for (int j = 0; j < 2; j++) {
                const uint32_t bo = swz(brow_base + j * 16, bchunk0 + ks * 2);
                uint32_t r0, r1, r2, r3;
                ldsm4(st + BHI_OFF + bo, r0, r1, r2, r3);
                bh[2 * j][0] = r0; bh[2 * j][1] = r1; bh[2 * j + 1][0] = r2; bh[2 * j + 1][1] = r3;
                ldsm4(st + BLO_OFF + bo, r0, r1, r2, r3);
                bl[2 * j][0] = r0; bl[2 * j][1] = r1; bl[2 * j + 1][0] = r2; bl[2 * j + 1][1] = r3;
            }
#pragma unroll
            for (int mt = 0; mt < 4; mt++)
#pragma unroll
                for (int nt = 0; nt < 4; nt++) mma_f16(acc[mt][nt], ah[mt], bh[nt]);
#pragma unroll
            for (int mt = 0; mt < 4; mt++)
#pragma unroll
                for (int nt = 0; nt < 4; nt++) mma_f16(acc[mt][nt], ah[mt], bl[nt]);
#pragma unroll
            for (int mt = 0; mt < 4; mt++)
#pragma unroll
                for (int nt = 0; nt < 4; nt++) mma_f16(acc[mt][nt], al[mt], bh[nt]);
        }
    }

    // ---- epilogue ----
    const int rr = lane >> 2, cb = (lane & 3) * 2;
#pragma unroll
    for (int mt = 0; mt < 4; mt++) {
#pragma unroll
        for (int nt = 0; nt < 4; nt++) {
            const int row = m0 + wm * 64 + mt * 16 + rr;
            const int col = n0 + wn * 32 + nt * 8 + cb;
            const float s0 = acc[mt][nt][0], s1 = acc[mt][nt][1];
            const float s2 = acc[mt][nt][2], s3 = acc[mt][nt][3];
            if (OUTMODE == 0) {
                float* base = Cf + (long long)bz * sC;
                stg_cs_f2(base + (long long)row * ldc + col, s0, s1);
                stg_cs_f2(base + (long long)(row + 8) * ldc + col, s2, s3);
            } else {
                f16* oh = Chi + (long long)bz * sC;
                f16* ol = Clo + (long long)bz * sC;
                f16 h0 = __float2half(s0), h1 = __float2half(s1);
                f16 h2 = __float2half(s2), h3 = __float2half(s3);
                f16 l0 = __float2half(s0 - __half2float(h0));
                f16 l1 = __float2half(s1 - __half2float(h1));
                f16 l2 = __float2half(s2 - __half2float(h2));
                f16 l3 = __float2half(s3 - __half2float(h3));
                *(__half2*)(oh + (long long)row * ldc + col)       = __halves2half2(h0, h1);
                *(__half2*)(oh + (long long)(row + 8) * ldc + col) = __halves2half2(h2, h3);
                *(__half2*)(ol + (long long)row * ldc + col)       = __halves2half2(l0, l1);
                *(__half2*)(ol + (long long)(row + 8) * ldc + col) = __halves2half2(l2, l3);
            }
        }
    }
}

// ===========================================================================
// K4: out[t][c] = -sum_s wei[t][s] * xH[s][c]
// 1-pass fp16 GEMM; K clamped, LPT, 4-stage pipeline, 2 CTA/SM.
// ===========================================================================
#define W_A   0
#define W_B   8192
#define W_STG 16896              // 8192 + 32*272
#define W_NST 4
#define W_SMEM (W_NST * W_STG)   // 67584

__global__ __launch_bounds__(256, 2) void gemm_wei(
    const f16* __restrict__ Wei,
    const f16* __restrict__ Bh,
    float* __restrict__ Out)
{
    const int bx = blockIdx.x, bz = blockIdx.z;
    const int by = (int)gridDim.y - 1 - (int)blockIdx.y;   // LPT
    const f16* wei = Wei + (long long)bz * TT * TT;
    const f16* bhi = Bh + (long long)bz * TT * CC;
    float* out = Out + (long long)bz * TT * CC;

    const int m0 = by * 128, n0 = bx * 128;
    const int Klim = min(TT, (by + 1) * 128);
    const int nc = Klim / 32;

    extern __shared__ char smem[];
    const uint32_t sbase = smem_u32(smem);
    const int tid = threadIdx.x;
    const int wid = tid >> 5, lane = tid & 31;
    const int wm = wid & 1, wn = wid >> 1;
    const int g = lane >> 3, i = lane & 7;

    const int arow_base = wm * 64 + i + (g & 1) * 8;
    const int achunk0 = g >> 1;
    const uint32_t bLaneT = (uint32_t)((lane & 15) * 272 + (lane >> 4) * 16 + wn * 64);

    const int l_row = tid >> 2, l_ch = tid & 3;
    const uint32_t l_soff0 = swz(l_row, l_ch);
    const uint32_t l_soff1 = swz(l_row + 64, l_ch);

    float acc[4][4][4];
#pragma unroll
    for (int a = 0; a < 4; a++)
#pragma unroll
        for (int b = 0; b < 4; b++)
#pragma unroll
            for (int c = 0; c < 4; c++) acc[a][b][c] = 0.f;

    auto issue = [&](int ch) {
        const uint32_t st = sbase + (uint32_t)(ch % W_NST) * W_STG;
        const long long k0 = (long long)ch * 32 + l_ch * 8;
        {
            cp16(st + W_A + l_soff0, wei + (long long)(m0 + l_row) * TT + k0);
            cp16(st + W_A + l_soff1, wei + (long long)(m0 + l_row + 64) * TT + k0);
        }
        const long long kb = (long long)ch * 32;
#pragma unroll
        for (int r = 0; r < 2; r++) {
            const int idx = tid + r * 256;
            const int brow = idx >> 4, bseg = idx & 15;
            const long long go = (kb + brow) * CC + n0 + bseg * 8;
            const uint32_t so = (uint32_t)(brow * 272 + bseg * 16);
            cp16(st + W_B + so, bhi + go);
        }
    };

#pragma unroll
    for (int s = 0; s < W_NST - 1; s++) {
        if (s < nc) issue(s);
        asm volatile("cp.async.commit_group;" ::: "memory");
    }

    for (int ch = 0; ch < nc; ch++) {
        asm volatile("cp.async.wait_group %0;" :: "n"(W_NST - 2) : "memory");
        __syncthreads();
        if (ch + W_NST - 1 < nc) issue(ch + W_NST - 1);
        asm volatile("cp.async.commit_group;" ::: "memory");

        const uint32_t st = sbase + (uint32_t)(ch % W_NST) * W_STG;

#pragma unroll
        for (int ks = 0; ks < 2; ks++) {
            uint32_t ah[4][4], bh[4][2];
#pragma unroll
            for (int mt = 0; mt < 4; mt++) {
                const uint32_t ao = swz(arow_base + mt * 16, achunk0 + ks * 2);
                ldsm4(st + W_A + ao, ah[mt][0], ah[mt][1], ah[mt][2], ah[mt][3]);
            }
#pragma unroll
            for (int j = 0; j < 2; j++) {
                uint32_t r0, r1, r2, r3;
                ldsm4t(st + W_B + bLaneT + ks * (16 * 272) + j * 32, r0, r1, r2, r3);
                bh[2 * j][0] = r0; bh[2 * j][1] = r1; bh[2 * j + 1][0] = r2; bh[2 * j + 1][1] = r3;
            }
#pragma unroll
            for (int mt = 0; mt < 4; mt++)
#pragma unroll
                for (int nt = 0; nt < 4; nt++) mma_f16(acc[mt][nt], ah[mt], bh[nt]);
        }
    }

    const int rr = lane >> 2, cb = (lane & 3) * 2;
#pragma unroll
    for (int mt = 0; mt < 4; mt++) {
#pragma unroll
        for (int nt = 0; nt < 4; nt++) {
            const int row = m0 + wm * 64 + mt * 16 + rr;
            const int col = n0 + wn * 32 + nt * 8 + cb;
            *(float2*)(out + (long long)row * CC + col) =
                make_float2(-acc[mt][nt][0], -acc[mt][nt][1]);
            *(float2*)(out + (long long)(row + 8) * CC + col) =
                make_float2(-acc[mt][nt][2], -acc[mt][nt][3]);
        }
    }
}

// ===========================================================================
// fp32 -> fp16 hi/lo split, fused for x then W
// ===========================================================================
__global__ __launch_bounds__(256) void split_f16_fused(
    const float* __restrict__ xsrc, f16* __restrict__ xh, f16* __restrict__ xl, long long n4x,
    const float* __restrict__ wsrc, f16* __restrict__ wh, f16* __restrict__ wl, long long n4w)
{
    const long long total = n4x + n4w;
    for (long long q = (long long)blockIdx.x * 256 + threadIdx.x; q < total;
         q += (long long)gridDim.x * 256) {
        const float4 v = (q < n4x) ? ((const float4*)xsrc)[q]
                                   : ((const float4*)wsrc)[q - n4x];
        const f16 h0 = __float2half(v.x), h1 = __float2half(v.y);
        const f16 h2 = __float2half(v.z), h3 = __float2half(v.w);
        const f16 l0 = __float2half(v.x - __half2float(h0));
        const f16 l1 = __float2half(v.y - __half2float(h1));
        const f16 l2 = __float2half(v.z - __half2float(h2));
        const f16 l3 = __float2half(v.w - __half2float(h3));
        __half2 hh[2] = { __halves2half2(h0, h1), __halves2half2(h2, h3) };
        __half2 ll[2] = { __halves2half2(l0, l1), __halves2half2(l2, l3) };
        if (q < n4x) {
            *(uint2*)(xh + q * 4) = *(uint2*)hh;
            *(uint2*)(xl + q * 4) = *(uint2*)ll;
        } else {
            *(uint2*)(wh + (q - n4x) * 4) = *(uint2*)hh;
            *(uint2*)(wl + (q - n4x) * 4) = *(uint2*)ll;
        }
    }
}

// ===========================================================================
// Causal softmax: register-resident, 2 complementary rows per block
// (t and TT-1-t: combined work is constant -> perfectly balanced grid).
// Online single-round reduction: per-warp (m_w, s_w) pairs, one barrier.
// Writes only s < ((t>>7)+1)*128.
// ===========================================================================
__global__ __launch_bounds__(256) void softmax_causal(
    const float* __restrict__ sc, f16* __restrict__ wout)
{
    const int b = blockIdx.x >> 10;          // batch
    const int j = blockIdx.x & 1023;         // row pair index
    const int tid = threadIdx.x;
    const int s0 = tid * 8;
    const int wrp = tid >> 5, lane = tid & 31;

    __shared__ float2 red[8];

#pragma unroll
    for (int half = 0; half < 2; half++) {
        const int t = half ? (TT - 1 - j) : j;
        const long long row = (long long)b * TT + t;
        const float* p = sc + row * TT;
        f16* oh = wout + row * TT;
        const int wlim = ((t >> 7) + 1) << 7;

        // ---- load 8 values (masked) ----
        float v[8];
        if (s0 < t) {
            const float4 a = ldg_cs_f4(p + s0);
            const float4 c = ldg_cs_f4(p + s0 + 4);
            v[0] = a.x; v[1] = a.y; v[2] = a.z; v[3] = a.w;
            v[4] = c.x; v[5] = c.y; v[6] = c.z; v[7] = c.w;
#pragma unroll
            for (int e = 0; e < 8; e++)
                if (s0 + e >= t) v[e] = -3.0e38f;
        } else {
#pragma unroll
            for (int e = 0; e < 8; e++) v[e] = -3.0e38f;
        }

        // ---- warp-local max and sum of exp(v - m_w) ----
        float mw = v[0];
#pragma unroll
        for (int e = 1; e < 8; e++) mw = fmaxf(mw, v[e]);
#pragma unroll
        for (int o = 16; o; o >>= 1) mw = fmaxf(mw, __shfl_xor_sync(0xffffffffu, mw, o));

        float sw = 0.0f;
#pragma unroll
        for (int e = 0; e < 8; e++) {
            v[e] = (s0 + e < t) ? __expf(v[e] - mw) : 0.0f;
            sw += v[e];
        }
#pragma unroll
        for (int o = 16; o; o >>= 1) sw += __shfl_xor_sync(0xffffffffu, sw, o);

        if (lane == 0) red[wrp] = make_float2(mw, sw);
        __syncthreads();

        // ---- combine 8 warp pairs (every thread) ----
        float m = red[0].x;
#pragma unroll
        for (int w = 1; w < 8; w++) m = fmaxf(m, red[w].x);
        float sum = 0.0f;
#pragma unroll
        for (int w = 0; w < 8; w++) sum += red[w].y * __expf(red[w].x - m);

        // rescale local exps to global max; inv handles t=0 (sum=0 -> inv=0)
        const float scale = __expf(mw - m);
        const float inv = (t > 0) ? (scale / sum) : 0.0f;

        // ---- store 8 fp16 (one uint4) inside K4 read region ----
        if (s0 < wlim) {
            __half2 h[4];
#pragma unroll
            for (int e = 0; e < 8; e += 2)
                h[e / 2] = __halves2half2(__float2half(v[e] * inv),
                                          __float2half(v[e + 1] * inv));
            *(uint4*)(oh + s0) = *(uint4*)h;
        }
        if (half == 0) __syncthreads();   // red[] reuse guard
    }
}

// ===========================================================================
extern "C" void kernel_launch(void* const* d_in, const int* in_sizes, int n_in,
                              void* d_out, int out_size)
{
    const float* x = (const float*)d_in[0];
    const float* W = (const float*)d_in[1];
    float* out = (float*)d_out;

    f16 *xhi, *xlo, *whi, *wlo, *xHhi, *xHlo, *wei;
    float* sc;
    cudaGetSymbolAddress((void**)&xhi,  g_xhi);
    cudaGetSymbolAddress((void**)&xlo,  g_xlo);
    cudaGetSymbolAddress((void**)&whi,  g_whi);
    cudaGetSymbolAddress((void**)&wlo,  g_wlo);
    cudaGetSymbolAddress((void**)&xHhi, g_xHhi);
    cudaGetSymbolAddress((void**)&xHlo, g_xHlo);
    cudaGetSymbolAddress((void**)&wei,  g_wei);
    cudaGetSymbolAddress((void**)&sc,   g_sc);

    cudaFuncSetAttribute(gemm_3x<false, 2>,
                         cudaFuncAttributeMaxDynamicSharedMemorySize, SMEM_TOTAL);
    cudaFuncSetAttribute(gemm_3x<true, 0>,
                         cudaFuncAttributeMaxDynamicSharedMemorySize, SMEM_TOTAL);
    cudaFuncSetAttribute(gemm_wei,
                         cudaFuncAttributeMaxDynamicSharedMemorySize, W_SMEM);

    // fused split: x then W
    split_f16_fused<<<4352, 256>>>(
        x, xhi, xlo, (long long)BB * TT * CC / 4,
        W, whi, wlo, (long long)CC * CC / 4);

    // K1: xH = x @ W^T  -> fp16 hi/lo  (3-pass)
    gemm_3x<false, 2><<<dim3(CC / 128, (BB * TT) / 128, 1), 256, SMEM_TOTAL>>>(
        xhi, xlo, whi, wlo, nullptr, xHhi, xHlo,
        CC, CC, CC, CC, 0, 0, 0);

    // K2: scores(fp32) = x @ xH^T per batch, exact lower-triangle grid (3-pass)
    {
        const int ntiles = (TT / 128) * (TT / 128 + 1) / 2;   // 136
        gemm_3x<true, 0><<<dim3(ntiles, 1, BB), 256, SMEM_TOTAL>>>(
            xhi, xlo, xHhi, xHlo, sc, nullptr, nullptr,
            CC, CC, TT, CC,
            (long long)TT * CC, (long long)TT * CC, (long long)TT * TT);
    }

    // K3: causal softmax -> wei fp16 (2 balanced rows/block, 1-round reduce)
    softmax_causal<<<BB * TT / 2, 256>>>(sc, wei);

    // K4: out = -(wei @ xHhi), 1-pass fp16, K clamped, LPT, 4-stage
    gemm_wei<<<dim3(CC / 128, TT / 128, BB), 256, W_SMEM>>>(
        wei, xHhi, out);
}

// round 17
// speedup vs baseline: 1.0036x; 1.0036x over previous
#include <cuda_runtime.h>
#include <cuda_fp16.h>
#include <cstdint>
#include <cmath>

#define BB 8
#define TT 2048
#define CC 1024

typedef __half f16;

// Scratch (device globals — allocation-free)
__device__ f16    g_xhi  [(size_t)BB * TT * CC];
__device__ f16    g_xlo  [(size_t)BB * TT * CC];
__device__ f16    g_whi  [(size_t)CC * CC];
__device__ f16    g_wlo  [(size_t)CC * CC];
__device__ f16    g_xHhi [(size_t)BB * TT * CC];
__device__ f16    g_xHlo [(size_t)BB * TT * CC];
__device__ float  g_sc   [(size_t)BB * TT * TT];
__device__ f16    g_wei  [(size_t)BB * TT * TT];

// ===========================================================================
// helpers
// ===========================================================================
__device__ __forceinline__ uint32_t smem_u32(const void* p) {
    uint32_t a;
    asm("{ .reg .u64 t; cvta.to.shared.u64 t, %1; cvt.u32.u64 %0, t; }" : "=r"(a) : "l"(p));
    return a;
}
__device__ __forceinline__ void cp16(uint32_t s, const void* g) {
    asm volatile("cp.async.cg.shared.global [%0], [%1], 16;" :: "r"(s), "l"(g) : "memory");
}
__device__ __forceinline__ void ldsm4(uint32_t addr, uint32_t& r0, uint32_t& r1,
                                      uint32_t& r2, uint32_t& r3) {
    asm volatile("ldmatrix.sync.aligned.m8n8.x4.shared.b16 {%0,%1,%2,%3}, [%4];"
                 : "=r"(r0), "=r"(r1), "=r"(r2), "=r"(r3) : "r"(addr));
}
__device__ __forceinline__ void ldsm4t(uint32_t addr, uint32_t& r0, uint32_t& r1,
                                       uint32_t& r2, uint32_t& r3) {
    asm volatile("ldmatrix.sync.aligned.m8n8.x4.trans.shared.b16 {%0,%1,%2,%3}, [%4];"
                 : "=r"(r0), "=r"(r1), "=r"(r2), "=r"(r3) : "r"(addr));
}
__device__ __forceinline__ void mma_f16(float c[4], const uint32_t a[4], const uint32_t b[2]) {
    asm volatile(
        "mma.sync.aligned.m16n8k16.row.col.f32.f16.f16.f32 "
        "{%0,%1,%2,%3}, {%4,%5,%6,%7}, {%8,%9}, {%0,%1,%2,%3};"
        : "+f"(c[0]), "+f"(c[1]), "+f"(c[2]), "+f"(c[3])
        : "r"(a[0]), "r"(a[1]), "r"(a[2]), "r"(a[3]), "r"(b[0]), "r"(b[1]));
}
__device__ __forceinline__ void stg_cs_f2(float* p, float a, float b) {
    asm volatile("st.global.cs.v2.f32 [%0], {%1, %2};" :: "l"(p), "f"(a), "f"(b) : "memory");
}

// swizzled 16B-chunk offset within a 128x32-f16 (64B-row) K-major tile
__device__ __forceinline__ uint32_t swz(int row, int chunk) {
    return (uint32_t)(row * 64 + ((chunk ^ ((row >> 1) & 3)) << 4));
}

// ===========================================================================
// 3xFP16 GEMM:  C = A[M,K] @ B[N,K]^T, fp16 hi/lo inputs, 128x128 tile, KC=32
// 3-stage cp.async pipeline, swizzled 64B rows, 2 CTAs/SM.
// CAUSAL: 1-D lower-triangle grid. OUTMODE: 0 = fp32 (.cs), 2 = fp16 hi/lo.
// ===========================================================================
#define AHI_OFF 0
#define ALO_OFF 8192
#define BHI_OFF 16384
#define BLO_OFF 24576
#define STG_BYTES 32768
#define SMEM_TOTAL (3 * STG_BYTES)   // 98304

template <bool CAUSAL, int OUTMODE>
__global__ __launch_bounds__(256, 2) void gemm_3x(
    const f16* __restrict__ Ahi, const f16* __restrict__ Alo,
    const f16* __restrict__ Bhi, const f16* __restrict__ Blo,
    float* __restrict__ Cf, f16* __restrict__ Chi, f16* __restrict__ Clo,
    int lda, int ldb, int ldc, int Kfull,
    long long sA, long long sB, long long sC)
{
    int bx, by;
    const int bz = blockIdx.z;
    if (CAUSAL) {
        const int idx = blockIdx.x;
        int t = (int)((sqrtf(8.0f * idx + 1.0f) - 1.0f) * 0.5f);
        while ((t + 1) * (t + 2) / 2 <= idx) t++;
        while (t * (t + 1) / 2 > idx) t--;
        by = t;
        bx = idx - t * (t + 1) / 2;
    } else {
        bx = blockIdx.x; by = blockIdx.y;
    }

    Ahi += (long long)bz * sA; Alo += (long long)bz * sA;
    Bhi += (long long)bz * sB; Blo += (long long)bz * sB;

    const int m0 = by * 128, n0 = bx * 128;
    const int nc = Kfull / 32;

    extern __shared__ char smem[];
    const uint32_t sbase = smem_u32(smem);
    const int tid = threadIdx.x;
    const int wid = tid >> 5, lane = tid & 31;
    const int wm = wid & 1, wn = wid >> 1;
    const int g = lane >> 3, i = lane & 7;

    const int arow_base = wm * 64 + i + (g & 1) * 8;
    const int brow_base = wn * 32 + i + (g >> 1) * 8;
    const int achunk0 = g >> 1;
    const int bchunk0 = g & 1;

    const int l_row = tid >> 2, l_ch = tid & 3;
    const uint32_t l_soff0 = swz(l_row, l_ch);
    const uint32_t l_soff1 = swz(l_row + 64, l_ch);

    float acc[4][4][4];
#pragma unroll
    for (int a = 0; a < 4; a++)
#pragma unroll
        for (int b = 0; b < 4; b++)
#pragma unroll
            for (int c = 0; c < 4; c++) acc[a][b][c] = 0.f;

    auto issue = [&](int ch) {
        const uint32_t st = sbase + (uint32_t)(ch % 3) * STG_BYTES;
        const long long k0 = (long long)ch * 32 + l_ch * 8;
        {
            const long long ga = (long long)(m0 + l_row) * lda + k0;
            const long long gb = (long long)(n0 + l_row) * ldb + k0;
            cp16(st + AHI_OFF + l_soff0, Ahi + ga);
            cp16(st + ALO_OFF + l_soff0, Alo + ga);
            cp16(st + BHI_OFF + l_soff0, Bhi + gb);
            cp16(st + BLO_OFF + l_soff0, Blo + gb);
        }
        {
            const long long ga = (long long)(m0 + l_row + 64) * lda + k0;
            const long long gb = (long long)(n0 + l_row + 64) * ldb + k0;
            cp16(st + AHI_OFF + l_soff1, Ahi + ga);
            cp16(st + ALO_OFF + l_soff1, Alo + ga);
            cp16(st + BHI_OFF + l_soff1, Bhi + gb);
            cp16(st + BLO_OFF + l_soff1, Blo + gb);
        }
    };

#pragma unroll
    for (int s = 0; s < 2; s++) {
        if (s < nc) issue(s);
        asm volatile("cp.async.commit_group;" ::: "memory");
    }

    for (int ch = 0; ch < nc; ch++) {
        asm volatile("cp.async.wait_group 1;" ::: "memory");
        __syncthreads();
        if (ch + 2 < nc) issue(ch + 2);
        asm volatile("cp.async.commit_group;" ::: "memory");

        const uint32_t st = sbase + (uint32_t)(ch % 3) * STG_BYTES;

#pragma unroll
        for (int ks = 0; ks < 2; ks++) {
            uint32_t ah[4][4], al[4][4], bh[4][2], bl[4][2];
#pragma unroll
            for (int mt = 0; mt < 4; mt++) {
                const uint32_t ao = swz(arow_base + mt * 16, achunk0 + ks * 2);
                ldsm4(st + AHI_OFF + ao, ah[mt][0], ah[mt][1], ah[mt][2], ah[mt][3]);
                ldsm4(st + ALO_OFF + ao, al[mt][0], al[mt][1], al[mt][2], al[mt][3]);
            }
#pragma unroll
            for (int j = 0; j < 2; j++) {
                const uint32_t bo = swz(brow_base + j * 16, bchunk0 + ks * 2);
                uint32_t r0, r1, r2, r3;
                ldsm4(st + BHI_OFF + bo, r0, r1, r2, r3);
                bh[2 * j][0] = r0; bh[2 * j][1] = r1; bh[2 * j + 1][0] = r2; bh[2 * j + 1][1] = r3;
                ldsm4(st + BLO_OFF + bo, r0, r1, r2, r3);
                bl[2 * j][0] = r0; bl[2 * j][1] = r1; bl[2 * j + 1][0] = r2; bl[2 * j + 1][1] = r3;
            }
#pragma unroll
            for (int mt = 0; mt < 4; mt++)
#pragma unroll
                for (int nt = 0; nt < 4; nt++) mma_f16(acc[mt][nt], ah[mt], bh[nt]);
#pragma unroll
            for (int mt = 0; mt < 4; mt++)
#pragma unroll
                for (int nt = 0; nt < 4; nt++) mma_f16(acc[mt][nt], ah[mt], bl[nt]);
#pragma unroll
            for (int mt = 0; mt < 4; mt++)
#pragma unroll
                for (int nt = 0; nt < 4; nt++) mma_f16(acc[mt][nt], al[mt], bh[nt]);
        }
    }

    // ---- epilogue ----
    const int rr = lane >> 2, cb = (lane & 3) * 2;
#pragma unroll
    for (int mt = 0; mt < 4; mt++) {
#pragma unroll
        for (int nt = 0; nt < 4; nt++) {
            const int row = m0 + wm * 64 + mt * 16 + rr;
            const int col = n0 + wn * 32 + nt * 8 + cb;
            const float s0 = acc[mt][nt][0], s1 = acc[mt][nt][1];
            const float s2 = acc[mt][nt][2], s3 = acc[mt][nt][3];
            if (OUTMODE == 0) {
                float* base = Cf + (long long)bz * sC;
                stg_cs_f2(base + (long long)row * ldc + col, s0, s1);
                stg_cs_f2(base + (long long)(row + 8) * ldc + col, s2, s3);
            } else {
                f16* oh = Chi + (long long)bz * sC;
                f16* ol = Clo + (long long)bz * sC;
                f16 h0 = __float2half(s0), h1 = __float2half(s1);
                f16 h2 = __float2half(s2), h3 = __float2half(s3);
                f16 l0 = __float2half(s0 - __half2float(h0));
                f16 l1 = __float2half(s1 - __half2float(h1));
                f16 l2 = __float2half(s2 - __half2float(h2));
                f16 l3 = __float2half(s3 - __half2float(h3));
                *(__half2*)(oh + (long long)row * ldc + col)       = __halves2half2(h0, h1);
                *(__half2*)(oh + (long long)(row + 8) * ldc + col) = __halves2half2(h2, h3);
                *(__half2*)(ol + (long long)row * ldc + col)       = __halves2half2(l0, l1);
                *(__half2*)(ol + (long long)(row + 8) * ldc + col) = __halves2half2(l2, l3);
            }
        }
    }
}

// ===========================================================================
// K4: out[t][c] = -sum_s wei[t][s] * xH[s][c]
// 1-pass fp16 GEMM; K clamped, LPT, 4-stage pipeline, 2 CTA/SM.
// ===========================================================================
#define W_A   0
#define W_B   8192
#define W_STG 16896              // 8192 + 32*272
#define W_NST 4
#define W_SMEM (W_NST * W_STG)   // 67584

__global__ __launch_bounds__(256, 2) void gemm_wei(
    const f16* __restrict__ Wei,
    const f16* __restrict__ Bh,
    float* __restrict__ Out)
{
    const int bx = blockIdx.x, bz = blockIdx.z;
    const int by = (int)gridDim.y - 1 - (int)blockIdx.y;   // LPT
    const f16* wei = Wei + (long long)bz * TT * TT;
    const f16* bhi = Bh + (long long)bz * TT * CC;
    float* out = Out + (long long)bz * TT * CC;

    const int m0 = by * 128, n0 = bx * 128;
    const int Klim = min(TT, (by + 1) * 128);
    const int nc = Klim / 32;

    extern __shared__ char smem[];
    const uint32_t sbase = smem_u32(smem);
    const int tid = threadIdx.x;
    const int wid = tid >> 5, lane = tid & 31;
    const int wm = wid & 1, wn = wid >> 1;
    const int g = lane >> 3, i = lane & 7;

    const int arow_base = wm * 64 + i + (g & 1) * 8;
    const int achunk0 = g >> 1;
    const uint32_t bLaneT = (uint32_t)((lane & 15) * 272 + (lane >> 4) * 16 + wn * 64);

    const int l_row = tid >> 2, l_ch = tid & 3;
    const uint32_t l_soff0 = swz(l_row, l_ch);
    const uint32_t l_soff1 = swz(l_row + 64, l_ch);

    float acc[4][4][4];
#pragma unroll
    for (int a = 0; a < 4; a++)
#pragma unroll
        for (int b = 0; b < 4; b++)
#pragma unroll
            for (int c = 0; c < 4; c++) acc[a][b][c] = 0.f;

    auto issue = [&](int ch) {
        const uint32_t st = sbase + (uint32_t)(ch % W_NST) * W_STG;
        const long long k0 = (long long)ch * 32 + l_ch * 8;
        {
            cp16(st + W_A + l_soff0, wei + (long long)(m0 + l_row) * TT + k0);
            cp16(st + W_A + l_soff1, wei + (long long)(m0 + l_row + 64) * TT + k0);
        }
        const long long kb = (long long)ch * 32;
#pragma unroll
        for (int r = 0; r < 2; r++) {
            const int idx = tid + r * 256;
            const int brow = idx >> 4, bseg = idx & 15;
            const long long go = (kb + brow) * CC + n0 + bseg * 8;
            const uint32_t so = (uint32_t)(brow * 272 + bseg * 16);
            cp16(st + W_B + so, bhi + go);
        }
    };

#pragma unroll
    for (int s = 0; s < W_NST - 1; s++) {
        if (s < nc) issue(s);
        asm volatile("cp.async.commit_group;" ::: "memory");
    }

    for (int ch = 0; ch < nc; ch++) {
        asm volatile("cp.async.wait_group %0;" :: "n"(W_NST - 2) : "memory");
        __syncthreads();
        if (ch + W_NST - 1 < nc) issue(ch + W_NST - 1);
        asm volatile("cp.async.commit_group;" ::: "memory");

        const uint32_t st = sbase + (uint32_t)(ch % W_NST) * W_STG;

#pragma unroll
        for (int ks = 0; ks < 2; ks++) {
            uint32_t ah[4][4], bh[4][2];
#pragma unroll
            for (int mt = 0; mt < 4; mt++) {
                const uint32_t ao = swz(arow_base + mt * 16, achunk0 + ks * 2);
                ldsm4(st + W_A + ao, ah[mt][0], ah[mt][1], ah[mt][2], ah[mt][3]);
            }
#pragma unroll
            for (int j = 0; j < 2; j++) {
                uint32_t r0, r1, r2, r3;
                ldsm4t(st + W_B + bLaneT + ks * (16 * 272) + j * 32, r0, r1, r2, r3);
                bh[2 * j][0] = r0; bh[2 * j][1] = r1; bh[2 * j + 1][0] = r2; bh[2 * j + 1][1] = r3;
            }
#pragma unroll
            for (int mt = 0; mt < 4; mt++)
#pragma unroll
                for (int nt = 0; nt < 4; nt++) mma_f16(acc[mt][nt], ah[mt], bh[nt]);
        }
    }

    const int rr = lane >> 2, cb = (lane & 3) * 2;
#pragma unroll
    for (int mt = 0; mt < 4; mt++) {
#pragma unroll
        for (int nt = 0; nt < 4; nt++) {
            const int row = m0 + wm * 64 + mt * 16 + rr;
            const int col = n0 + wn * 32 + nt * 8 + cb;
            *(float2*)(out + (long long)row * CC + col) =
                make_float2(-acc[mt][nt][0], -acc[mt][nt][1]);
            *(float2*)(out + (long long)(row + 8) * CC + col) =
                make_float2(-acc[mt][nt][2], -acc[mt][nt][3]);
        }
    }
}

// ===========================================================================
// fp32 -> fp16 hi/lo split, fused for x then W
// ===========================================================================
__global__ __launch_bounds__(256) void split_f16_fused(
    const float* __restrict__ xsrc, f16* __restrict__ xh, f16* __restrict__ xl, long long n4x,
    const float* __restrict__ wsrc, f16* __restrict__ wh, f16* __restrict__ wl, long long n4w)
{
    const long long total = n4x + n4w;
    for (long long q = (long long)blockIdx.x * 256 + threadIdx.x; q < total;
         q += (long long)gridDim.x * 256) {
        const float4 v = (q < n4x) ? ((const float4*)xsrc)[q]
                                   : ((const float4*)wsrc)[q - n4x];
        const f16 h0 = __float2half(v.x), h1 = __float2half(v.y);
        const f16 h2 = __float2half(v.z), h3 = __float2half(v.w);
        const f16 l0 = __float2half(v.x - __half2float(h0));
        const f16 l1 = __float2half(v.y - __half2float(h1));
        const f16 l2 = __float2half(v.z - __half2float(h2));
        const f16 l3 = __float2half(v.w - __half2float(h3));
        __half2 hh[2] = { __halves2half2(h0, h1), __halves2half2(h2, h3) };
        __half2 ll[2] = { __halves2half2(l0, l1), __halves2half2(l2, l3) };
        if (q < n4x) {
            *(uint2*)(xh + q * 4) = *(uint2*)hh;
            *(uint2*)(xl + q * 4) = *(uint2*)ll;
        } else {
            *(uint2*)(wh + (q - n4x) * 4) = *(uint2*)hh;
            *(uint2*)(wl + (q - n4x) * 4) = *(uint2*)ll;
        }
    }
}

// ===========================================================================
// Causal softmax: register-resident, ONE row per block (R15 geometry),
// online single-barrier reduction: per-warp (m_w, s_w), one __syncthreads,
// every thread combines 8 pairs. Writes only s < ((t>>7)+1)*128; LPT.
// ===========================================================================
__global__ __launch_bounds__(256) void softmax_causal(
    const float* __restrict__ sc, f16* __restrict__ wout)
{
    const long long row = (long long)(BB * TT - 1) - blockIdx.x;   // LPT
    const int t = (int)(row % TT);
    const float* p = sc + row * TT;
    f16* oh = wout + row * TT;
    const int tid = threadIdx.x;
    const int s0 = tid * 8;
    const int wrp = tid >> 5, lane = tid & 31;
    const int wlim = ((t >> 7) + 1) << 7;

    __shared__ float2 red[8];

    // ---- load 8 values into registers (masked) ----
    float v[8];
    if (s0 < t) {
        const float4 a = *(const float4*)(p + s0);
        const float4 b = *(const float4*)(p + s0 + 4);
        v[0] = a.x; v[1] = a.y; v[2] = a.z; v[3] = a.w;
        v[4] = b.x; v[5] = b.y; v[6] = b.z; v[7] = b.w;
#pragma unroll
        for (int e = 0; e < 8; e++)
            if (s0 + e >= t) v[e] = -3.0e38f;
    } else {
#pragma unroll
        for (int e = 0; e < 8; e++) v[e] = -3.0e38f;
    }

    // ---- warp-local max, then exp relative to warp max + warp sum ----
    float mw = v[0];
#pragma unroll
    for (int e = 1; e < 8; e++) mw = fmaxf(mw, v[e]);
#pragma unroll
    for (int o = 16; o; o >>= 1) mw = fmaxf(mw, __shfl_xor_sync(0xffffffffu, mw, o));

    float sw = 0.0f;
#pragma unroll
    for (int e = 0; e < 8; e++) {
        v[e] = (s0 + e < t) ? __expf(v[e] - mw) : 0.0f;
        sw += v[e];
    }
#pragma unroll
    for (int o = 16; o; o >>= 1) sw += __shfl_xor_sync(0xffffffffu, sw, o);

    if (lane == 0) red[wrp] = make_float2(mw, sw);
    __syncthreads();

    // ---- combine 8 warp pairs (every thread, no second barrier) ----
    float m = red[0].x;
#pragma unroll
    for (int w = 1; w < 8; w++) m = fmaxf(m, red[w].x);
    float sum = 0.0f;
#pragma unroll
    for (int w = 0; w < 8; w++) sum += red[w].y * __expf(red[w].x - m);

    const float inv = (t > 0) ? (__expf(mw - m) / sum) : 0.0f;

    // ---- store 8 fp16 (one uint4) inside K4 read region ----
    if (s0 < wlim) {
        __half2 h[4];
#pragma unroll
        for (int e = 0; e < 8; e += 2)
            h[e / 2] = __halves2half2(__float2half(v[e] * inv),
                                      __float2half(v[e + 1] * inv));
        *(uint4*)(oh + s0) = *(uint4*)h;
    }
}

// ===========================================================================
extern "C" void kernel_launch(void* const* d_in, const int* in_sizes, int n_in,
                              void* d_out, int out_size)
{
    const float* x = (const float*)d_in[0];
    const float* W = (const float*)d_in[1];
    float* out = (float*)d_out;

    f16 *xhi, *xlo, *whi, *wlo, *xHhi, *xHlo, *wei;
    float* sc;
    cudaGetSymbolAddress((void**)&xhi,  g_xhi);
    cudaGetSymbolAddress((void**)&xlo,  g_xlo);
    cudaGetSymbolAddress((void**)&whi,  g_whi);
    cudaGetSymbolAddress((void**)&wlo,  g_wlo);
    cudaGetSymbolAddress((void**)&xHhi, g_xHhi);
    cudaGetSymbolAddress((void**)&xHlo, g_xHlo);
    cudaGetSymbolAddress((void**)&wei,  g_wei);
    cudaGetSymbolAddress((void**)&sc,   g_sc);

    cudaFuncSetAttribute(gemm_3x<false, 2>,
                         cudaFuncAttributeMaxDynamicSharedMemorySize, SMEM_TOTAL);
    cudaFuncSetAttribute(gemm_3x<true, 0>,
                         cudaFuncAttributeMaxDynamicSharedMemorySize, SMEM_TOTAL);
    cudaFuncSetAttribute(gemm_wei,
                         cudaFuncAttributeMaxDynamicSharedMemorySize, W_SMEM);

    // fused split: x then W
    split_f16_fused<<<4352, 256>>>(
        x, xhi, xlo, (long long)BB * TT * CC / 4,
        W, whi, wlo, (long long)CC * CC / 4);

    // K1: xH = x @ W^T  -> fp16 hi/lo  (3-pass)
    gemm_3x<false, 2><<<dim3(CC / 128, (BB * TT) / 128, 1), 256, SMEM_TOTAL>>>(
        xhi, xlo, whi, wlo, nullptr, xHhi, xHlo,
        CC, CC, CC, CC, 0, 0, 0);

    // K2: scores(fp32) = x @ xH^T per batch, exact lower-triangle grid (3-pass)
    {
        const int ntiles = (TT / 128) * (TT / 128 + 1) / 2;   // 136
        gemm_3x<true, 0><<<dim3(ntiles, 1, BB), 256, SMEM_TOTAL>>>(
            xhi, xlo, xHhi, xHlo, sc, nullptr, nullptr,
            CC, CC, TT, CC,
            (long long)TT * CC, (long long)TT * CC, (long long)TT * TT);
    }

    // K3: causal softmax -> wei fp16 (1 row/block, single-barrier reduce, LPT)
    softmax_causal<<<BB * TT, 256>>>(sc, wei);

    // K4: out = -(wei @ xHhi), 1-pass fp16, K clamped, LPT, 4-stage
    gemm_wei<<<dim3(CC / 128, TT / 128, BB), 256, W_SMEM>>>(
        wei, xHhi, out);
}